// round 2
// baseline (speedup 1.0000x reference)
#include <cuda_runtime.h>
#include <cuda_bf16.h>
#include <cstdint>

// Problem shape (fixed by the dataset)
static constexpr int B = 4;
static constexpr int S = 4096;
static constexpr int D = 4096;

// Tiling
static constexpr int L  = 64;            // s-steps per chunk (held in registers)
static constexpr int C  = S / L;         // 64 chunks along S
static constexpr int TD = 256;           // channels per block (= threads per block)
static constexpr int NT = (B * D) / TD;  // 64 row tiles

// Scratch (static device globals — no dynamic allocation allowed)
__device__ float g_aggA[NT * C * TD];    // chunk aggregate A (prod of gates)
__device__ float g_aggB[NT * C * TD];    // chunk aggregate B (local scan tail)
__device__ float g_incl[NT * C * TD];    // inclusive prefix (state at end of chunk)
__device__ int   g_status[NT * C];       // 0=invalid, 1=aggregate ready, 2=inclusive ready

__global__ void __launch_bounds__(TD, 1)
assoc_scan_kernel(const float* __restrict__ gates,
                  const float* __restrict__ inputs,
                  const float* __restrict__ prev,
                  float* __restrict__ out)
{
    const int c = blockIdx.x;            // chunk index along S (fastest -> lower id = earlier chunk)
    const int y = blockIdx.y;            // row tile: which 256-channel group
    const int t = threadIdx.x;

    const int tiles_per_batch = D / TD;  // 16
    const int b  = y / tiles_per_batch;
    const int dt = y % tiles_per_batch;
    const int d  = dt * TD + t;

    const size_t base = (size_t)b * S * D + (size_t)(c * L) * D + d;

    // ---- Phase 1: bulk load chunk into registers (max MLP, fully coalesced) ----
    float a[L], v[L];
#pragma unroll
    for (int i = 0; i < L; i++) a[i] = gates[base + (size_t)i * D];
#pragma unroll
    for (int i = 0; i < L; i++) v[i] = inputs[base + (size_t)i * D];

    // ---- Phase 2: local scan (two independent FFMA chains) ----
    // a[i] becomes cumulative product of gates, v[i] becomes local scan with zero init.
#pragma unroll
    for (int i = 1; i < L; i++) {
        v[i] = fmaf(a[i], v[i - 1], v[i]);
        a[i] = a[i] * a[i - 1];
    }

    const int sbase = y * C;
    const int aidx  = (sbase + c) * TD + t;
    __shared__ int sh_flag;

    // ---- Phase 3: resolve incoming state via decoupled lookback ----
    float s_in;
    if (c == 0) {
        s_in = prev[(size_t)b * D + d];
    } else {
        // Publish aggregate
        g_aggA[aidx] = a[L - 1];
        g_aggB[aidx] = v[L - 1];
        __threadfence();
        __syncthreads();
        if (t == 0) atomicExch(&g_status[sbase + c], 1);

        // Walk back, composing aggregates until an inclusive prefix is found.
        float accA = 1.0f, accB = 0.0f;
        int j = c - 1;
        for (;;) {
            if (t == 0) {
                int st;
                do {
                    st = atomicAdd(&g_status[sbase + j], 0);
                    if (st == 0) __nanosleep(40);
                } while (st == 0);
                sh_flag = st;
            }
            __syncthreads();
            const int st = sh_flag;
            __syncthreads();      // protect sh_flag before next iteration overwrite
            __threadfence();      // acquire: order scratch reads after flag observation

            const int jidx = (sbase + j) * TD + t;
            if (st == 2) {
                const float Vj = g_incl[jidx];
                s_in = fmaf(accA, Vj, accB);
                break;
            } else {
                const float Aj = g_aggA[jidx];
                const float Bj = g_aggB[jidx];
                accB = fmaf(accA, Bj, accB);
                accA = accA * Aj;
                j--;
                if (j < 0) {
                    s_in = fmaf(accA, prev[(size_t)b * D + d], accB);
                    break;
                }
            }
        }
    }

    // ---- Phase 4: publish inclusive prefix for successors ----
    if (c < C - 1) {
        g_incl[aidx] = fmaf(a[L - 1], s_in, v[L - 1]);
        __threadfence();
        __syncthreads();
        if (t == 0) atomicExch(&g_status[sbase + c], 2);
    }

    // ---- Phase 5: fix up and store (coalesced) ----
#pragma unroll
    for (int i = 0; i < L; i++) {
        out[base + (size_t)i * D] = fmaf(a[i], s_in, v[i]);
    }
}

extern "C" void kernel_launch(void* const* d_in, const int* in_sizes, int n_in,
                              void* d_out, int out_size)
{
    const float* gates  = (const float*)d_in[0];
    const float* inputs = (const float*)d_in[1];
    const float* prev   = (const float*)d_in[2];
    float* out          = (float*)d_out;

    // Reset lookback status flags (graph-capturable async memset, stream 0)
    void* status_ptr = nullptr;
    cudaGetSymbolAddress(&status_ptr, g_status);
    cudaMemsetAsync(status_ptr, 0, NT * C * sizeof(int));

    dim3 grid(C, NT);   // chunk fastest -> predecessor chunks have lower linear block id
    dim3 block(TD);
    assoc_scan_kernel<<<grid, block>>>(gates, inputs, prev, out);
}

// round 3
// speedup vs baseline: 1.2801x; 1.2801x over previous
#include <cuda_runtime.h>
#include <cuda_bf16.h>
#include <cstdint>

// Problem shape (fixed by the dataset)
static constexpr int B = 4;
static constexpr int S = 4096;
static constexpr int D = 4096;

// Tiling
static constexpr int L  = 64;            // s-steps per chunk (held in registers)
static constexpr int C  = S / L;         // 64 chunks along S (fits a 64-bit mask)
static constexpr int TD = 256;           // channels per block (= threads per block)
static constexpr int NT = (B * D) / TD;  // 64 row tiles

static_assert(C <= 64, "chunk mask must fit in 64 bits");

// Scratch (static device globals — no dynamic allocation allowed)
__device__ float              g_aggA[NT * C * TD];  // chunk aggregate A (prod of gates)
__device__ float              g_aggB[NT * C * TD];  // chunk aggregate B (local scan tail)
__device__ unsigned long long g_mask[NT];           // per-tile "aggregate published" bitmask

__global__ void __launch_bounds__(TD, 1)
assoc_scan_kernel(const float* __restrict__ gates,
                  const float* __restrict__ inputs,
                  const float* __restrict__ prev,
                  float* __restrict__ out)
{
    const int c = blockIdx.x;            // chunk index along S
    const int y = blockIdx.y;            // row tile: which 256-channel group
    const int t = threadIdx.x;

    const int tiles_per_batch = D / TD;  // 16
    const int b  = y / tiles_per_batch;
    const int dt = y % tiles_per_batch;
    const int d  = dt * TD + t;

    const size_t base = (size_t)b * S * D + (size_t)(c * L) * D + d;

    // ---- Phase 1: bulk load chunk into registers (streaming, fully coalesced) ----
    float a[L], v[L];
#pragma unroll
    for (int i = 0; i < L; i++) a[i] = __ldcs(&gates[base + (size_t)i * D]);
#pragma unroll
    for (int i = 0; i < L; i++) v[i] = __ldcs(&inputs[base + (size_t)i * D]);

    const float prevv = prev[(size_t)b * D + d];

    // ---- Phase 2: local scan (two independent FFMA chains) ----
    // a[i] -> cumulative gate product; v[i] -> local scan with zero initial state.
#pragma unroll
    for (int i = 1; i < L; i++) {
        v[i] = fmaf(a[i], v[i - 1], v[i]);
        a[i] = a[i] * a[i - 1];
    }

    const int sbase = y * C;
    const int aidx  = (sbase + c) * TD + t;
    __shared__ int sh_ready;

    // ---- Phase 3: publish this chunk's aggregate (no dependency on anything) ----
    if (c < C - 1) {   // last chunk has no successors; skip publish
        g_aggA[aidx] = a[L - 1];
        g_aggB[aidx] = v[L - 1];
        __threadfence();                 // release: aggregates visible before mask bit
        __syncthreads();                 // all threads' stores done before flag
        if (t == 0) atomicOr(&g_mask[y], 1ull << c);
    }

    // ---- Phase 4: wait for ALL predecessors' aggregates, then bulk-fold ----
    float s_in;
    if (c == 0) {
        s_in = prevv;
    } else {
        const unsigned long long need = (1ull << c) - 1ull;
        if (t == 0) {
            unsigned long long m;
            do {
                m = atomicOr(&g_mask[y], 0ull);   // L2 read-modify-read of the single word
                if ((m & need) == need) break;
                __nanosleep(60);
            } while (true);
            sh_ready = 1;
        }
        __syncthreads();
        (void)sh_ready;
        __threadfence();                 // acquire: order aggregate reads after flag

        // Fold predecessors newest -> oldest: acc := acc ∘ agg_j
        float accA = 1.0f, accB = 0.0f;
        for (int j = c - 1; j >= 0; j--) {
            const int jidx = (sbase + j) * TD + t;
            const float Aj = __ldcg(&g_aggA[jidx]);
            const float Bj = __ldcg(&g_aggB[jidx]);
            accB = fmaf(accA, Bj, accB);
            accA = accA * Aj;
        }
        s_in = fmaf(accA, prevv, accB);
    }

    // ---- Phase 5: fix up and store (streaming, coalesced) ----
#pragma unroll
    for (int i = 0; i < L; i++) {
        __stcs(&out[base + (size_t)i * D], fmaf(a[i], s_in, v[i]));
    }
}

extern "C" void kernel_launch(void* const* d_in, const int* in_sizes, int n_in,
                              void* d_out, int out_size)
{
    const float* gates  = (const float*)d_in[0];
    const float* inputs = (const float*)d_in[1];
    const float* prev   = (const float*)d_in[2];
    float* out          = (float*)d_out;

    // Reset publish bitmasks (graph-capturable async memset on stream 0)
    void* mask_ptr = nullptr;
    cudaGetSymbolAddress(&mask_ptr, g_mask);
    cudaMemsetAsync(mask_ptr, 0, NT * sizeof(unsigned long long));

    dim3 grid(C, NT);   // chunk fastest -> predecessors co-resident / earlier waves
    dim3 block(TD);
    assoc_scan_kernel<<<grid, block>>>(gates, inputs, prev, out);
}

// round 4
// speedup vs baseline: 2.0950x; 1.6366x over previous
#include <cuda_runtime.h>
#include <cuda_bf16.h>
#include <cstdint>

// Problem shape (fixed by the dataset)
static constexpr int B  = 4;
static constexpr int S  = 4096;
static constexpr int D  = 4096;
static constexpr int D4 = D / 4;             // 1024 float4 per (b, s) row

// Tiling
static constexpr int L     = 64;             // s-steps per chunk
static constexpr int C     = S / L;          // 64 chunks along S (fits 64-bit mask)
static constexpr int CH    = 32;             // float4 channel-groups per block (=128 scalar channels)
static constexpr int SEG   = 8;              // s-segments per chunk within a block
static constexpr int STEPS = L / SEG;        // 8 steps per thread
static constexpr int TD    = CH * SEG;       // 256 threads
static constexpr int NT    = (B * D4) / CH;  // 128 row tiles

static_assert(C <= 64, "chunk mask must fit in 64 bits");

// Scratch (static device globals — no dynamic allocation allowed)
__device__ float4             g_aggA[NT * C * CH];  // chunk aggregate A (gate product)
__device__ float4             g_aggB[NT * C * CH];  // chunk aggregate B (local scan tail)
__device__ unsigned long long g_mask[NT];           // per-tile publish bitmask

__device__ __forceinline__ float4 f4_fma(float4 a, float4 b, float4 c) {
    return make_float4(fmaf(a.x, b.x, c.x), fmaf(a.y, b.y, c.y),
                       fmaf(a.z, b.z, c.z), fmaf(a.w, b.w, c.w));
}
__device__ __forceinline__ float4 f4_mul(float4 a, float4 b) {
    return make_float4(a.x * b.x, a.y * b.y, a.z * b.z, a.w * b.w);
}

__global__ void __launch_bounds__(TD, 2)
assoc_scan_kernel(const float4* __restrict__ gates,
                  const float4* __restrict__ inputs,
                  const float4* __restrict__ prev,
                  float4* __restrict__ out)
{
    const int c   = blockIdx.x;          // chunk along S (fastest -> predecessors earlier/co-resident)
    const int y   = blockIdx.y;          // row tile
    const int t   = threadIdx.x;
    const int gi  = t % CH;              // channel-group within tile
    const int seg = t / CH;              // s-segment within chunk

    const int g    = y * CH + gi;        // global float4 channel-group
    const int b    = g / D4;
    const int col4 = g % D4;

    const size_t base = (size_t)b * S * D4 + (size_t)(c * L + seg * STEPS) * D4 + col4;

    // ---- Phase 1: bulk vectorized load (streaming, fully coalesced) ----
    float4 a[STEPS], v[STEPS];
#pragma unroll
    for (int i = 0; i < STEPS; i++) a[i] = __ldcs(&gates[base + (size_t)i * D4]);
#pragma unroll
    for (int i = 0; i < STEPS; i++) v[i] = __ldcs(&inputs[base + (size_t)i * D4]);

    const float4 pv = prev[(size_t)b * D4 + col4];

    // ---- Phase 2: local scan within segment ----
    // a[i] -> cumulative gate product within segment; v[i] -> local scan, zero init.
#pragma unroll
    for (int i = 1; i < STEPS; i++) {
        v[i] = f4_fma(a[i], v[i - 1], v[i]);
        a[i] = f4_mul(a[i], a[i - 1]);
    }

    __shared__ float4 shA[SEG][CH];
    __shared__ float4 shB[SEG][CH];
    __shared__ float4 sh_sin[CH];

    // ---- Phase 3: intra-chunk exclusive prefix over segments ----
    shA[seg][gi] = a[STEPS - 1];
    shB[seg][gi] = v[STEPS - 1];
    __syncthreads();

    float4 PA = make_float4(1.f, 1.f, 1.f, 1.f);
    float4 PB = make_float4(0.f, 0.f, 0.f, 0.f);
#pragma unroll
    for (int j = 0; j < SEG; j++) {      // P_seg = f_{seg-1} ∘ ... ∘ f_0
        if (j < seg) {
            const float4 Aj = shA[j][gi];
            const float4 Bj = shB[j][gi];
            PB = f4_fma(Aj, PB, Bj);
            PA = f4_mul(Aj, PA);
        }
    }

    // ---- Phase 4: publish chunk aggregate (f_7 ∘ P_7, by seg==7 threads) ----
    if (c < C - 1) {
        if (seg == SEG - 1) {
            const float4 CA = f4_mul(a[STEPS - 1], PA);
            const float4 CB = f4_fma(a[STEPS - 1], PB, v[STEPS - 1]);
            const int aidx = (y * C + c) * CH + gi;
            g_aggA[aidx] = CA;
            g_aggB[aidx] = CB;
            __threadfence();             // release: aggregates visible before mask bit
        }
        __syncthreads();
        if (t == 0) atomicOr(&g_mask[y], 1ull << c);
    }

    // ---- Phase 5: resolve incoming state (sliced parallel fold over predecessors) ----
    float4 sin_;
    if (c == 0) {
        sin_ = pv;
    } else {
        if (t == 0) {
            const unsigned long long need = (1ull << c) - 1ull;
            while ((atomicOr(&g_mask[y], 0ull) & need) != need) __nanosleep(40);
        }
        __syncthreads();
        __threadfence();                 // acquire: order aggregate reads after flag

        // Each segment folds a contiguous slice of [0, c), newest-first within slice.
        const int len = (c + SEG - 1) / SEG;
        const int lo  = seg * len;
        const int hi  = min(lo + len, c);
        float4 FA = make_float4(1.f, 1.f, 1.f, 1.f);
        float4 FB = make_float4(0.f, 0.f, 0.f, 0.f);
        for (int j = hi - 1; j >= lo; j--) {
            const int jidx = (y * C + j) * CH + gi;
            const float4 Aj = __ldcg(&g_aggA[jidx]);
            const float4 Bj = __ldcg(&g_aggB[jidx]);
            FB = f4_fma(FA, Bj, FB);     // acc = acc ∘ f_j
            FA = f4_mul(FA, Aj);
        }

        shA[seg][gi] = FA;               // overwrite is safe: sync above separates readers
        shB[seg][gi] = FB;
        __syncthreads();

        if (seg == 0) {                  // combine 8 slice-partials oldest -> newest
            float4 TA = make_float4(1.f, 1.f, 1.f, 1.f);
            float4 TB = make_float4(0.f, 0.f, 0.f, 0.f);
#pragma unroll
            for (int k = 0; k < SEG; k++) {
                const float4 Ak = shA[k][gi];
                const float4 Bk = shB[k][gi];
                TB = f4_fma(Ak, TB, Bk); // total = G_k ∘ total
                TA = f4_mul(Ak, TA);
            }
            sh_sin[gi] = f4_fma(TA, pv, TB);
        }
        __syncthreads();
        sin_ = sh_sin[gi];
    }

    // ---- Phase 6: fix up and store (vectorized streaming) ----
    const float4 ss = f4_fma(PA, sin_, PB);   // state at the start of this segment
#pragma unroll
    for (int i = 0; i < STEPS; i++) {
        __stcs(&out[base + (size_t)i * D4], f4_fma(a[i], ss, v[i]));
    }
}

extern "C" void kernel_launch(void* const* d_in, const int* in_sizes, int n_in,
                              void* d_out, int out_size)
{
    const float4* gates  = (const float4*)d_in[0];
    const float4* inputs = (const float4*)d_in[1];
    const float4* prev   = (const float4*)d_in[2];
    float4* out          = (float4*)d_out;

    // Reset publish bitmasks (graph-capturable async memset on stream 0)
    void* mask_ptr = nullptr;
    cudaGetSymbolAddress(&mask_ptr, g_mask);
    cudaMemsetAsync(mask_ptr, 0, NT * sizeof(unsigned long long));

    dim3 grid(C, NT);   // chunk fastest -> predecessors co-resident / earlier waves
    dim3 block(TD);
    assoc_scan_kernel<<<grid, block>>>(gates, inputs, prev, out);
}